// round 4
// baseline (speedup 1.0000x reference)
#include <cuda_runtime.h>
#include <cuda_bf16.h>
#include <cstdint>

// Problem constants
#define BATCH 64
#define CIN   64
#define H     128
#define W     128
#define COUT  256
#define OH    126
#define OW    126
#define MTOT  (OH*OW)     // 15876 output positions per image
#define KTOT  (CIN*9)     // 576  reduction dim
#define KSTEPS (KTOT/16)  // 36

// Scratch (allocation-free per harness rules: __device__ globals)
__device__ __nv_bfloat16 g_xbf[(size_t)BATCH*CIN*H*W];   // 134 MB
__device__ __nv_bfloat16 g_wbf[KTOT*COUT];               // [k][co], 288 KB

// ---------------- prologue kernels ----------------

__global__ void cvt_x_kernel(const float* __restrict__ x) {
    size_t i = (size_t)blockIdx.x * blockDim.x + threadIdx.x;   // over n/4
    float4 v = reinterpret_cast<const float4*>(x)[i];
    __nv_bfloat162* dst = reinterpret_cast<__nv_bfloat162*>(g_xbf);
    dst[2*i]   = __floats2bfloat162_rn(v.x, v.y);
    dst[2*i+1] = __floats2bfloat162_rn(v.z, v.w);
}

__global__ void cvt_w_kernel(const float* __restrict__ w) {
    // w is OIHW: w[co][ci][kh][kw] = w[co*576 + k]. Store transposed: g_wbf[k][co].
    int k = blockIdx.x;     // 0..575
    int n = threadIdx.x;    // 0..255
    g_wbf[k*COUT + n] = __float2bfloat16(w[n*KTOT + k]);
}

__global__ void zero_kernel(float* out) {
    out[blockIdx.x * blockDim.x + threadIdx.x] = 0.0f;
}

// ---------------- main implicit-GEMM kernel ----------------

#define PM 136   // smem pitch (elements): 272B rows -> conflict-free ldmatrix.trans

__device__ __forceinline__ uint32_t smem_u32(const void* p) {
    return (uint32_t)__cvta_generic_to_shared(p);
}

__device__ __forceinline__ void ldsm4t(uint32_t& r0, uint32_t& r1, uint32_t& r2,
                                       uint32_t& r3, uint32_t addr) {
    asm volatile("ldmatrix.sync.aligned.m8n8.x4.trans.shared.b16 {%0,%1,%2,%3}, [%4];"
                 : "=r"(r0), "=r"(r1), "=r"(r2), "=r"(r3) : "r"(addr));
}

__device__ __forceinline__ void mma16816(float c[4],
                                         uint32_t a0, uint32_t a1, uint32_t a2, uint32_t a3,
                                         uint32_t b0, uint32_t b1) {
    asm volatile("mma.sync.aligned.m16n8k16.row.col.f32.bf16.bf16.f32 "
                 "{%0,%1,%2,%3}, {%4,%5,%6,%7}, {%8,%9}, {%0,%1,%2,%3};"
                 : "+f"(c[0]), "+f"(c[1]), "+f"(c[2]), "+f"(c[3])
                 : "r"(a0), "r"(a1), "r"(a2), "r"(a3), "r"(b0), "r"(b1));
}

__device__ __forceinline__ float gelu_tanh(float x) {
    float x3 = x * x * x;
    float u = 0.7978845608028654f * fmaf(0.044715f, x3, x);
    float t;
    asm("tanh.approx.f32 %0, %1;" : "=f"(t) : "f"(u));
    return 0.5f * x * (1.0f + t);
}

__global__ void __launch_bounds__(256, 2)
conv_gemm_kernel(const float* __restrict__ bias, float* __restrict__ out) {
    __shared__ __align__(16) __nv_bfloat16 As[2][16 * PM];  // [k][m]
    __shared__ __align__(16) __nv_bfloat16 Bs[2][16 * PM];  // [k][n]

    const int tid    = threadIdx.x;
    const int lane   = tid & 31;
    const int warp   = tid >> 5;
    const int warp_m = warp >> 2;    // 0..1 -> 64 rows each
    const int warp_n = warp & 3;     // 0..3 -> 32 cols each
    const int m0 = blockIdx.x * 128;
    const int n0 = blockIdx.y * 128;
    const int b  = blockIdx.z;

    // Per-thread gather coordinates (fixed across all K-steps)
    const int tm = tid & 127;
    int m_clamped = m0 + tm;
    if (m_clamped >= MTOT) m_clamped = 0;        // clamp; masked in epilogue
    const int oh = m_clamped / OW;
    const int ow = m_clamped - oh * OW;
    const __nv_bfloat16* xb = g_xbf + ((size_t)b * CIN) * (H * W) + oh * W + ow;
    const __nv_bfloat16* wb = g_wbf + n0 + tm;
    const int krow = tid >> 7;                   // 0 or 1

    // Prologue: K-step 0 -> buffer 0
    #pragma unroll
    for (int i = 0; i < 8; i++) {
        int k  = krow + 2 * i;
        int ci = k / 9;
        int r  = k - ci * 9;
        int kh = r / 3;
        int kw = r - kh * 3;
        As[0][k * PM + tm] = xb[ci * (H * W) + kh * W + kw];
        Bs[0][k * PM + tm] = wb[(size_t)k * COUT];
    }
    __syncthreads();

    float acc[4][4][4];
    #pragma unroll
    for (int a = 0; a < 4; a++)
        #pragma unroll
        for (int c = 0; c < 4; c++)
            #pragma unroll
            for (int d = 0; d < 4; d++) acc[a][c][d] = 0.0f;

    // ldmatrix lane addressing (constant per lane)
    const int a_krow = (lane & 7) + ((lane & 16) >> 1);
    const int a_moff = warp_m * 64 + (lane & 8);
    const int b_krow = (lane & 7) + (lane & 8);
    const int b_noff = warp_n * 32 + ((lane & 16) >> 1);

    for (int kt = 0; kt < KSTEPS; kt++) {
        const int cur = kt & 1;

        // Stage next tile's gmem loads (overlap with MMA below)
        __nv_bfloat16 sa[8], sb[8];
        if (kt + 1 < KSTEPS) {
            const int kbase = (kt + 1) * 16 + krow;
            #pragma unroll
            for (int i = 0; i < 8; i++) {
                int k  = kbase + 2 * i;
                int ci = k / 9;
                int r  = k - ci * 9;
                int kh = r / 3;
                int kw = r - kh * 3;
                sa[i] = xb[ci * (H * W) + kh * W + kw];
                sb[i] = wb[(size_t)k * COUT];
            }
        }

        // Compute on buffer `cur`
        const uint32_t a_base = smem_u32(&As[cur][0]);
        const uint32_t b_base = smem_u32(&Bs[cur][0]);

        uint32_t afr[4][4];
        #pragma unroll
        for (int mi = 0; mi < 4; mi++) {
            uint32_t addr = a_base + (uint32_t)((a_krow * PM + a_moff + mi * 16) * 2);
            ldsm4t(afr[mi][0], afr[mi][1], afr[mi][2], afr[mi][3], addr);
        }
        uint32_t bfr[4][2];
        #pragma unroll
        for (int q = 0; q < 2; q++) {
            uint32_t addr = b_base + (uint32_t)((b_krow * PM + b_noff + q * 16) * 2);
            ldsm4t(bfr[2*q][0], bfr[2*q][1], bfr[2*q+1][0], bfr[2*q+1][1], addr);
        }
        #pragma unroll
        for (int mi = 0; mi < 4; mi++)
            #pragma unroll
            for (int ni = 0; ni < 4; ni++)
                mma16816(acc[mi][ni],
                         afr[mi][0], afr[mi][1], afr[mi][2], afr[mi][3],
                         bfr[ni][0], bfr[ni][1]);

        if (kt + 1 < KSTEPS) {
            const int nxt = cur ^ 1;
            #pragma unroll
            for (int i = 0; i < 8; i++) {
                int kl = krow + 2 * i;
                As[nxt][kl * PM + tm] = sa[i];
                Bs[nxt][kl * PM + tm] = sb[i];
            }
        }
        __syncthreads();
    }

    // Epilogue: bias + GELU + partial spatial-mean reduction
    const int group = lane >> 2;
    const int tid4  = lane & 3;

    float bcol[8];
    #pragma unroll
    for (int j = 0; j < 8; j++) {
        int ni = j >> 1, bsel = j & 1;
        bcol[j] = bias[n0 + warp_n * 32 + ni * 8 + tid4 * 2 + bsel];
    }

    float csum[8];
    #pragma unroll
    for (int j = 0; j < 8; j++) csum[j] = 0.0f;

    #pragma unroll
    for (int mi = 0; mi < 4; mi++) {
        #pragma unroll
        for (int half = 0; half < 2; half++) {
            int mrow = m0 + warp_m * 64 + mi * 16 + half * 8 + group;
            bool ok = (mrow < MTOT);
            #pragma unroll
            for (int ni = 0; ni < 4; ni++) {
                #pragma unroll
                for (int bsel = 0; bsel < 2; bsel++) {
                    if (ok) {
                        float y = acc[mi][ni][half * 2 + bsel] + bcol[ni * 2 + bsel];
                        csum[ni * 2 + bsel] += gelu_tanh(y);
                    }
                }
            }
        }
    }

    // Reduce over lane groups sharing the same columns (bits 2..4 of lane)
    #pragma unroll
    for (int j = 0; j < 8; j++) {
        csum[j] += __shfl_xor_sync(0xffffffffu, csum[j], 16);
        csum[j] += __shfl_xor_sync(0xffffffffu, csum[j], 8);
        csum[j] += __shfl_xor_sync(0xffffffffu, csum[j], 4);
    }

    if (lane < 4) {
        const float inv = 1.0f / (float)MTOT;
        #pragma unroll
        for (int j = 0; j < 8; j++) {
            int ni = j >> 1, bsel = j & 1;
            int n = n0 + warp_n * 32 + ni * 8 + tid4 * 2 + bsel;
            atomicAdd(&out[b * COUT + n], csum[j] * inv);
        }
    }
}

// ---------------- launch ----------------

extern "C" void kernel_launch(void* const* d_in, const int* in_sizes, int n_in,
                              void* d_out, int out_size) {
    const float* x    = (const float*)d_in[0];   // [64,64,128,128]
    const float* w    = (const float*)d_in[1];   // [256,64,3,3]
    const float* bias = (const float*)d_in[2];   // [256]
    float* out = (float*)d_out;                  // [64,256]

    // 1) convert x to bf16 scratch (67,108,864 elems / 4 per thread)
    cvt_x_kernel<<<65536, 256>>>(x);
    // 2) convert + transpose weights to [K][N] bf16
    cvt_w_kernel<<<KTOT, COUT>>>(w);
    // 3) zero the output accumulator
    zero_kernel<<<(BATCH * COUT) / 256, 256>>>(out);
    // 4) fused conv(implicit GEMM) + bias + GELU + mean-pool
    dim3 grid((MTOT + 127) / 128, COUT / 128, BATCH);   // (125, 2, 64)
    conv_gemm_kernel<<<grid, 256>>>(bias, out);
}

// round 5
// speedup vs baseline: 1.8075x; 1.8075x over previous
#include <cuda_runtime.h>
#include <cuda_bf16.h>
#include <cstdint>

// Problem constants
#define BATCH 64
#define CIN   64
#define H     128
#define W     128
#define HW    (H*W)
#define COUT  256
#define OH    126
#define OW    126
#define MTOT  (OH*OW)     // 15876
#define KTOT  (CIN*9)     // 576
#define KSTEPS (KTOT/16)  // 36

static const size_t XN = (size_t)BATCH * CIN * H * W;   // 67,108,864

// Scratch (__device__ globals: allocation-free per harness rules)
// Three copies of x in bf16, shifted left by 0/1/2 elements (kw shift baked in)
__device__ __align__(16) __nv_bfloat16 g_xs[3][(size_t)BATCH*CIN*H*W + 64];
// Weights transposed + K-reordered: g_wbf[k'][co], k' = (kh*3+kw)*64 + ci
__device__ __align__(16) __nv_bfloat16 g_wbf[KTOT*COUT];

// ---------------- prologue kernels ----------------

__device__ __forceinline__ uint32_t packbf(float lo, float hi) {
    __nv_bfloat162 h = __floats2bfloat162_rn(lo, hi);
    return *reinterpret_cast<uint32_t*>(&h);
}

__global__ void cvt_x3_kernel(const float* __restrict__ x) {
    size_t p = ((size_t)blockIdx.x * blockDim.x + threadIdx.x) * 8;
    float4 a = *reinterpret_cast<const float4*>(x + p);
    float4 b = *reinterpret_cast<const float4*>(x + p + 4);
    float cx = 0.f, cy = 0.f;
    if (p + 8 < XN) cx = x[p + 8];
    if (p + 9 < XN) cy = x[p + 9];
    uint32_t r0 = packbf(a.x, a.y);
    uint32_t r1 = packbf(a.z, a.w);
    uint32_t r2 = packbf(b.x, b.y);
    uint32_t r3 = packbf(b.z, b.w);
    uint32_t r4 = packbf(cx, cy);
    // shift-0
    *reinterpret_cast<uint4*>(&g_xs[0][p]) = make_uint4(r0, r1, r2, r3);
    // shift-1: elements p+1..p+8
    uint32_t v0 = __funnelshift_r(r0, r1, 16);
    uint32_t v1 = __funnelshift_r(r1, r2, 16);
    uint32_t v2 = __funnelshift_r(r2, r3, 16);
    uint32_t v3 = __funnelshift_r(r3, r4, 16);
    *reinterpret_cast<uint4*>(&g_xs[1][p]) = make_uint4(v0, v1, v2, v3);
    // shift-2: elements p+2..p+9
    *reinterpret_cast<uint4*>(&g_xs[2][p]) = make_uint4(r1, r2, r3, r4);
}

__global__ void cvt_w_kernel(const float* __restrict__ w) {
    // k' = khw*64 + ci ; original k = ci*9 + khw
    int kp = blockIdx.x;       // 0..575
    int n  = threadIdx.x;      // 0..255
    int ci  = kp & 63;
    int khw = kp >> 6;
    g_wbf[kp * COUT + n] = __float2bfloat16(w[n * KTOT + ci * 9 + khw]);
}

__global__ void zero_kernel(float* out) {
    out[blockIdx.x * blockDim.x + threadIdx.x] = 0.0f;
}

// ---------------- main implicit-GEMM kernel ----------------

#define PM 136   // A smem pitch (272B rows, conflict-free trans ldmatrix)
#define PN 264   // B smem pitch (528B rows)
#define STG 4

__device__ __forceinline__ uint32_t smem_u32(const void* p) {
    return (uint32_t)__cvta_generic_to_shared(p);
}

__device__ __forceinline__ void cp16(uint32_t dst, const void* src) {
    asm volatile("cp.async.cg.shared.global [%0], [%1], 16;\n" :: "r"(dst), "l"(src));
}

__device__ __forceinline__ void ldsm4t(uint32_t& r0, uint32_t& r1, uint32_t& r2,
                                       uint32_t& r3, uint32_t addr) {
    asm volatile("ldmatrix.sync.aligned.m8n8.x4.trans.shared.b16 {%0,%1,%2,%3}, [%4];"
                 : "=r"(r0), "=r"(r1), "=r"(r2), "=r"(r3) : "r"(addr));
}

__device__ __forceinline__ void mma16816(float c[4],
                                         uint32_t a0, uint32_t a1, uint32_t a2, uint32_t a3,
                                         uint32_t b0, uint32_t b1) {
    asm volatile("mma.sync.aligned.m16n8k16.row.col.f32.bf16.bf16.f32 "
                 "{%0,%1,%2,%3}, {%4,%5,%6,%7}, {%8,%9}, {%0,%1,%2,%3};"
                 : "+f"(c[0]), "+f"(c[1]), "+f"(c[2]), "+f"(c[3])
                 : "r"(a0), "r"(a1), "r"(a2), "r"(a3), "r"(b0), "r"(b1));
}

__device__ __forceinline__ float gelu_tanh(float x) {
    float x3 = x * x * x;
    float u = 0.7978845608028654f * fmaf(0.044715f, x3, x);
    float t;
    asm("tanh.approx.f32 %0, %1;" : "=f"(t) : "f"(u));
    return 0.5f * x * (1.0f + t);
}

__global__ void __launch_bounds__(512, 1)
conv_gemm_kernel(const float* __restrict__ bias, float* __restrict__ out) {
    __shared__ __align__(16) __nv_bfloat16 As[STG][16 * PM];
    __shared__ __align__(16) __nv_bfloat16 Bs[STG][16 * PN];

    const int tid    = threadIdx.x;
    const int lane   = tid & 31;
    const int warp   = tid >> 5;
    const int warp_m = warp >> 2;    // 0..3 -> 32 m-rows each
    const int warp_n = warp & 3;     // 0..3 -> 64 n-cols each
    const int oh = blockIdx.x;       // 0..125 (one output row per CTA)
    const int b  = blockIdx.y;

    // staging roles
    const int ak = tid >> 4, aj = tid & 15;   // threads 0..255: A chunk (k, 16B chunk)
    const int bk = tid >> 5, bj = tid & 31;   // all threads:   B chunk

    const size_t xrow = ((size_t)(b * CIN)) * HW + (size_t)oh * W;
    const __nv_bfloat16* wsrc = g_wbf + bk * COUT + bj * 8;
    const uint32_t a_sdst = smem_u32(&As[0][0]) + (ak * PM + aj * 8) * 2;
    const uint32_t b_sdst = smem_u32(&Bs[0][0]) + (bk * PN + bj * 8) * 2;

    // --- pipeline issue ---
    auto issue = [&](int kt) {
        const int slot = kt & (STG - 1);
        const int khw  = kt >> 2;
        const int kh   = (khw * 11) >> 5;     // floor(khw/3) for khw in [0,9)
        const int kw   = khw - kh * 3;
        const int ci0  = (kt & 3) * 16;
        if (tid < 256) {
            const __nv_bfloat16* src =
                g_xs[kw] + xrow + (size_t)(ci0 + ak) * HW + kh * W + aj * 8;
            cp16(a_sdst + slot * (16 * PM * 2), src);
        }
        cp16(b_sdst + slot * (16 * PN * 2), wsrc + (size_t)kt * 16 * COUT);
        asm volatile("cp.async.commit_group;\n" ::);
    };

    issue(0); issue(1); issue(2);

    float acc[2][8][4];
    #pragma unroll
    for (int mi = 0; mi < 2; mi++)
        #pragma unroll
        for (int ni = 0; ni < 8; ni++)
            #pragma unroll
            for (int d = 0; d < 4; d++) acc[mi][ni][d] = 0.0f;

    // ldmatrix lane addressing (constant per lane)
    const int a_krow = (lane & 7) + ((lane & 16) >> 1);
    const int a_moff = warp_m * 32 + (lane & 8);
    const int b_krow = (lane & 7) + (lane & 8);
    const int b_noff = warp_n * 64 + ((lane & 16) >> 1);

    for (int kt = 0; kt < KSTEPS; kt++) {
        asm volatile("cp.async.wait_group 2;\n" ::);
        __syncthreads();
        if (kt + 3 < KSTEPS) issue(kt + 3);
        else asm volatile("cp.async.commit_group;\n" ::);

        const int slot = kt & (STG - 1);
        const uint32_t a_base = smem_u32(&As[slot][0]);
        const uint32_t b_base = smem_u32(&Bs[slot][0]);

        uint32_t afr[2][4];
        #pragma unroll
        for (int mi = 0; mi < 2; mi++) {
            uint32_t addr = a_base + (uint32_t)((a_krow * PM + a_moff + mi * 16) * 2);
            ldsm4t(afr[mi][0], afr[mi][1], afr[mi][2], afr[mi][3], addr);
        }
        uint32_t bfr[8][2];
        #pragma unroll
        for (int q = 0; q < 4; q++) {
            uint32_t addr = b_base + (uint32_t)((b_krow * PN + b_noff + q * 16) * 2);
            ldsm4t(bfr[2*q][0], bfr[2*q][1], bfr[2*q+1][0], bfr[2*q+1][1], addr);
        }
        #pragma unroll
        for (int mi = 0; mi < 2; mi++)
            #pragma unroll
            for (int ni = 0; ni < 8; ni++)
                mma16816(acc[mi][ni],
                         afr[mi][0], afr[mi][1], afr[mi][2], afr[mi][3],
                         bfr[ni][0], bfr[ni][1]);
    }

    // ---- epilogue: bias + GELU + row-mean partial reduction ----
    const int group = lane >> 2;
    const int tid4  = lane & 3;

    float bcol[16];
    #pragma unroll
    for (int j = 0; j < 16; j++) {
        int ni = j >> 1, bs = j & 1;
        bcol[j] = bias[warp_n * 64 + ni * 8 + tid4 * 2 + bs];
    }

    float csum[16];
    #pragma unroll
    for (int j = 0; j < 16; j++) csum[j] = 0.0f;

    #pragma unroll
    for (int mi = 0; mi < 2; mi++) {
        #pragma unroll
        for (int half = 0; half < 2; half++) {
            int ow = warp_m * 32 + mi * 16 + half * 8 + group;
            bool ok = (ow < OW);
            #pragma unroll
            for (int ni = 0; ni < 8; ni++) {
                #pragma unroll
                for (int bs = 0; bs < 2; bs++) {
                    if (ok) {
                        float y = acc[mi][ni][half * 2 + bs] + bcol[ni * 2 + bs];
                        csum[ni * 2 + bs] += gelu_tanh(y);
                    }
                }
            }
        }
    }

    // reduce over the 8 lane-groups holding the same columns
    #pragma unroll
    for (int j = 0; j < 16; j++) {
        csum[j] += __shfl_xor_sync(0xffffffffu, csum[j], 16);
        csum[j] += __shfl_xor_sync(0xffffffffu, csum[j], 8);
        csum[j] += __shfl_xor_sync(0xffffffffu, csum[j], 4);
    }

    if (lane < 4) {
        const float inv = 1.0f / (float)MTOT;
        #pragma unroll
        for (int j = 0; j < 16; j++) {
            int ni = j >> 1, bs = j & 1;
            int n = warp_n * 64 + ni * 8 + tid4 * 2 + bs;
            atomicAdd(&out[b * COUT + n], csum[j] * inv);
        }
    }
}

// ---------------- launch ----------------

extern "C" void kernel_launch(void* const* d_in, const int* in_sizes, int n_in,
                              void* d_out, int out_size) {
    const float* x    = (const float*)d_in[0];   // [64,64,128,128]
    const float* w    = (const float*)d_in[1];   // [256,64,3,3]
    const float* bias = (const float*)d_in[2];   // [256]
    float* out = (float*)d_out;                  // [64,256]

    // 1) x -> bf16, three kw-shifted aligned copies
    cvt_x3_kernel<<<32768, 256>>>(x);
    // 2) weights -> bf16, K-reordered [k'][co]
    cvt_w_kernel<<<KTOT, COUT>>>(w);
    // 3) zero output accumulator
    zero_kernel<<<(BATCH * COUT) / 256, 256>>>(out);
    // 4) fused implicit-GEMM conv + bias + GELU + mean-pool
    dim3 grid(OH, BATCH);    // (126, 64): one output row per CTA, full N=256
    conv_gemm_kernel<<<grid, 512>>>(bias, out);
}